// round 4
// baseline (speedup 1.0000x reference)
#include <cuda_runtime.h>
#include <cuda_fp16.h>
#include <math.h>

#define B_SZ     8192
#define FPP      32
#define FT_OUT   1024
#define N_FEAT   49152
#define N_VFEAT  768

// int8 combined table (bytes biased +128): row f = 1024 bytes.  48 MiB -> L2-resident.
__device__ unsigned int g_wq[(size_t)N_FEAT * (FT_OUT / 4)];
__device__ float        g_qscale[N_FEAT];   // per-row quant step q (w = (u-128)*q)

// ---------------------------------------------------------------------------
// Kernel 1: build combined table, quantize to int8 with per-row scale.
// One CTA (128 thr) per feature row; thread owns 8 columns.
// W_ft streamed with __ldcs (evict-first) to protect L2 residency of g_wq.
// ---------------------------------------------------------------------------
__global__ __launch_bounds__(128) void build_wq_kernel(
    const float* __restrict__ W_ft,
    const float* __restrict__ W_fft)
{
    const int f  = blockIdx.x;
    const int t  = threadIdx.x;
    const int c  = t * 8;
    const int fv = f % N_VFEAT;

    const float4* a = reinterpret_cast<const float4*>(W_ft  + (size_t)f  * FT_OUT + c);
    const float4* v = reinterpret_cast<const float4*>(W_fft + (size_t)fv * FT_OUT + c);
    const float4 a0 = __ldcs(a), a1 = __ldcs(a + 1);
    const float4 v0 = __ldg(v),  v1 = __ldg(v + 1);

    float w[8];
    w[0] = a0.x + v0.x; w[1] = a0.y + v0.y; w[2] = a0.z + v0.z; w[3] = a0.w + v0.w;
    w[4] = a1.x + v1.x; w[5] = a1.y + v1.y; w[6] = a1.z + v1.z; w[7] = a1.w + v1.w;

    float m = 0.f;
#pragma unroll
    for (int i = 0; i < 8; ++i) m = fmaxf(m, fabsf(w[i]));

#pragma unroll
    for (int off = 16; off > 0; off >>= 1)
        m = fmaxf(m, __shfl_xor_sync(0xFFFFFFFFu, m, off));

    __shared__ float sm[4];
    const int warp = t >> 5, lane = t & 31;
    if (lane == 0) sm[warp] = m;
    __syncthreads();
    m = fmaxf(fmaxf(sm[0], sm[1]), fmaxf(sm[2], sm[3]));

    const float mm  = fmaxf(m, 1e-30f);
    const float inv = 127.0f / mm;
    if (t == 0) g_qscale[f] = mm * (1.0f / 127.0f);

    unsigned int lo = 0, hi = 0;
#pragma unroll
    for (int i = 0; i < 4; ++i) {
        int q = __float2int_rn(w[i] * inv) + 128;
        lo |= ((unsigned int)(q & 0xFF)) << (8 * i);
    }
#pragma unroll
    for (int i = 0; i < 4; ++i) {
        int q = __float2int_rn(w[4 + i] * inv) + 128;
        hi |= ((unsigned int)(q & 0xFF)) << (8 * i);
    }
    uint2 packed; packed.x = lo; packed.y = hi;
    reinterpret_cast<uint2*>(g_wq)[(size_t)f * (FT_OUT / 8) + t] = packed;
}

// ---------------------------------------------------------------------------
// Kernel 2: fused gather. 128 threads = 2 k-groups x 64 threads.
// Thread covers 16 columns (one LDG.128 per side per iter); group g handles
// k = g, g+2, g+4, ... (16 iterations). Partial fp16 accumulators merged via
// smem, then bias + clip + output dot + sigmoid.
// ---------------------------------------------------------------------------
__device__ __forceinline__ void unpack_fma(unsigned int u, __half2 vq,
                                           __half2& a0, __half2& a1)
{
    const __half2 C1152 = __float2half2_rn(1152.0f);
    unsigned int p0 = __byte_perm(u, 0x64646464u, 0x4140);   // {1024+b0, 1024+b1}
    unsigned int p1 = __byte_perm(u, 0x64646464u, 0x4342);   // {1024+b2, 1024+b3}
    __half2 h0 = __hsub2(*reinterpret_cast<__half2*>(&p0), C1152);  // exact ints
    __half2 h1 = __hsub2(*reinterpret_cast<__half2*>(&p1), C1152);
    a0 = __hfma2(h0, vq, a0);
    a1 = __hfma2(h1, vq, a1);
}

__global__ __launch_bounds__(128) void nnue_gather_kernel(
    const float* __restrict__ values,
    const int*   __restrict__ stm_feat,
    const int*   __restrict__ nstm_feat,
    const float* __restrict__ b_ft,
    const float* __restrict__ b_fft,
    const float* __restrict__ W_out,
    const float* __restrict__ b_out,
    float*       __restrict__ out)
{
    const int b  = blockIdx.x;
    const int t  = threadIdx.x;
    const int kg = t >> 6;           // k-group: 0 or 1
    const int ct = t & 63;           // column-thread within group
    const int coff = ct * 16;        // byte offset of this thread's 16 columns

    __shared__ uint4 s_meta[FPP];    // {off_s, off_n, vqs(bits), vqn(bits)}
    __shared__ __half2 s_accs[64][8];
    __shared__ __half2 s_accn[64][8];
    __shared__ float s_red[2];

    if (t < FPP) {
        const int   fs = stm_feat[b * FPP + t];
        const int   fn = nstm_feat[b * FPP + t];
        const float v  = values[b * FPP + t];
        const __half2 hs = __float2half2_rn(v * g_qscale[fs]);
        const __half2 hn = __float2half2_rn(v * g_qscale[fn]);
        uint4 m;
        m.x = (unsigned int)(fs << 10);
        m.y = (unsigned int)(fn << 10);
        m.z = *reinterpret_cast<const unsigned int*>(&hs);
        m.w = *reinterpret_cast<const unsigned int*>(&hn);
        s_meta[t] = m;
    }
    __syncthreads();

    const char* base = reinterpret_cast<const char*>(g_wq);

    __half2 accs[8], accn[8];
#pragma unroll
    for (int i = 0; i < 8; ++i) {
        accs[i] = __float2half2_rn(0.f);
        accn[i] = __float2half2_rn(0.f);
    }

#pragma unroll 8
    for (int k = kg; k < FPP; k += 2) {
        const uint4 meta = s_meta[k];
        const __half2 vqs = *reinterpret_cast<const __half2*>(&meta.z);
        const __half2 vqn = *reinterpret_cast<const __half2*>(&meta.w);

        const uint4 ws = *reinterpret_cast<const uint4*>(base + meta.x + coff);
        const uint4 wn = *reinterpret_cast<const uint4*>(base + meta.y + coff);

        unpack_fma(ws.x, vqs, accs[0], accs[1]);
        unpack_fma(ws.y, vqs, accs[2], accs[3]);
        unpack_fma(ws.z, vqs, accs[4], accs[5]);
        unpack_fma(ws.w, vqs, accs[6], accs[7]);
        unpack_fma(wn.x, vqn, accn[0], accn[1]);
        unpack_fma(wn.y, vqn, accn[2], accn[3]);
        unpack_fma(wn.z, vqn, accn[4], accn[5]);
        unpack_fma(wn.w, vqn, accn[6], accn[7]);
    }

    // group 1 publishes its partials; group 0 merges and finishes
    if (kg == 1) {
#pragma unroll
        for (int i = 0; i < 8; ++i) {
            s_accs[ct][i] = accs[i];
            s_accn[ct][i] = accn[i];
        }
    }
    __syncthreads();

    if (kg == 0) {
        const int col = ct * 16;
        float partial = 0.f;

#pragma unroll
        for (int i = 0; i < 8; ++i) {
            const __half2 ms = __hadd2(accs[i], s_accs[ct][i]);
            const __half2 mn = __hadd2(accn[i], s_accn[ct][i]);
            const float2 fs2 = __half22float2(ms);
            const float2 fn2 = __half22float2(mn);

            const int c0 = col + 2 * i;
            const float bias0 = b_ft[c0]     + b_fft[c0];
            const float bias1 = b_ft[c0 + 1] + b_fft[c0 + 1];

            const float xs0 = fminf(fmaxf(fs2.x + bias0, 0.f), 1.f);
            const float xs1 = fminf(fmaxf(fs2.y + bias1, 0.f), 1.f);
            const float xn0 = fminf(fmaxf(fn2.x + bias0, 0.f), 1.f);
            const float xn1 = fminf(fmaxf(fn2.y + bias1, 0.f), 1.f);

            partial = fmaf(xs0, W_out[c0],              partial);
            partial = fmaf(xs1, W_out[c0 + 1],          partial);
            partial = fmaf(xn0, W_out[FT_OUT + c0],     partial);
            partial = fmaf(xn1, W_out[FT_OUT + c0 + 1], partial);
        }

#pragma unroll
        for (int off = 16; off > 0; off >>= 1)
            partial += __shfl_down_sync(0xFFFFFFFFu, partial, off);

        const int warp = ct >> 5, lane = ct & 31;
        if (lane == 0) s_red[warp] = partial;
    }
    __syncthreads();

    if (t == 0) {
        const float z = s_red[0] + s_red[1] + b_out[0];
        out[b] = 1.0f / (1.0f + __expf(-z));
    }
}

extern "C" void kernel_launch(void* const* d_in, const int* in_sizes, int n_in,
                              void* d_out, int out_size) {
    const float* values    = (const float*)d_in[0];
    const int*   stm_feat  = (const int*)  d_in[1];
    const int*   nstm_feat = (const int*)  d_in[2];
    // d_in[3] = batch_idx (contiguous repeat(arange(B), 32) — unused)
    const float* W_ft      = (const float*)d_in[4];
    const float* b_ft      = (const float*)d_in[5];
    const float* W_fft     = (const float*)d_in[6];
    const float* b_fft     = (const float*)d_in[7];
    const float* W_out     = (const float*)d_in[8];
    const float* b_out     = (const float*)d_in[9];
    float*       out       = (float*)d_out;

    build_wq_kernel<<<N_FEAT, 128>>>(W_ft, W_fft);
    nnue_gather_kernel<<<B_SZ, 128>>>(values, stm_feat, nstm_feat,
                                      b_ft, b_fft, W_out, b_out, out);
}